// round 6
// baseline (speedup 1.0000x reference)
#include <cuda_runtime.h>
#include <math.h>

#define NB_MAX 400
#define NMAX   1024
#define WKER   0.05f
#define INV_WKER 20.0f
#define CUT    0.225f          // 4.5 sigma truncation
#define GNORM  7.9788456080f   // 1/(0.05*sqrt(2*pi))
#define PI_F   3.14159265358979f
#define HF     0.0025f         // fine-bin width = sigma/20
#define INV_HF 400.0f
#define MFINE_MAX 4608

__device__ float g_fine[MFINE_MAX];   // CIC-deposited pair-distance cloud
__device__ float g_hist[NB_MAX];      // KDE result (written fully by conv)

// ---------------------------------------------------------------------------
// Kernel 1: MIC pair distances + CIC deposit into fine histogram.
// Block b owns rows i=b and i=N-1-b (exactly N-1 pairs per block).
// 2 global float atomics per in-window pair (spread over ~4060 addresses).
// ---------------------------------------------------------------------------
__global__ void __launch_bounds__(256)
hist_kernel(const float* __restrict__ pos, const float* __restrict__ cell,
            const float* __restrict__ rb, int N, int nb) {
    __shared__ float s_pos[NMAX * 3];
    __shared__ float s_ci[9];
    __shared__ float s_c[9];
    __shared__ int   s_diag;
    int t = threadIdx.x;

    bool fits = (N <= NMAX);
    if (fits)
        for (int k = t; k < 3 * N; k += 256) s_pos[k] = pos[k];
    if (t == 0) {
        float m[9];
        #pragma unroll
        for (int i = 0; i < 9; i++) { m[i] = cell[i]; s_c[i] = m[i]; }
        float c00 =  (m[4]*m[8] - m[5]*m[7]);
        float c01 = -(m[3]*m[8] - m[5]*m[6]);
        float c02 =  (m[3]*m[7] - m[4]*m[6]);
        float det = m[0]*c00 + m[1]*c01 + m[2]*c02;
        float id  = 1.0f / det;
        s_ci[0] =  c00 * id;
        s_ci[1] = -(m[1]*m[8] - m[2]*m[7]) * id;
        s_ci[2] =  (m[1]*m[5] - m[2]*m[4]) * id;
        s_ci[3] =  c01 * id;
        s_ci[4] =  (m[0]*m[8] - m[2]*m[6]) * id;
        s_ci[5] = -(m[0]*m[5] - m[2]*m[3]) * id;
        s_ci[6] =  c02 * id;
        s_ci[7] = -(m[0]*m[7] - m[1]*m[6]) * id;
        s_ci[8] =  (m[0]*m[4] - m[1]*m[3]) * id;
        s_diag = (m[1]==0.f && m[2]==0.f && m[3]==0.f &&
                  m[5]==0.f && m[6]==0.f && m[7]==0.f) ? 1 : 0;
    }
    __syncthreads();

    const float* __restrict__ P = fits ? s_pos : pos;

    const float minb  = rb[0]      - 3.0f * WKER;
    const float maxb  = rb[nb - 1] + 3.0f * WKER;
    const float minb2 = (minb > 0.0f) ? minb * minb : -1.0f;
    const float maxb2 = maxb * maxb;
    int  M = (int)ceilf(maxb * INV_HF) + 1;
    if (M > MFINE_MAX) M = MFINE_MAX;
    const bool diag = (s_diag != 0);
    const float Lx = s_c[0], Ly = s_c[4], Lz = s_c[8];
    const float iLx = 1.0f / Lx, iLy = 1.0f / Ly, iLz = 1.0f / Lz;

    #pragma unroll
    for (int half = 0; half < 2; half++) {
        int i = (half == 0) ? (int)blockIdx.x : (N - 1 - (int)blockIdx.x);
        if (i < 0 || i >= N - 1) continue;
        float xi = P[3*i + 0], yi = P[3*i + 1], zi = P[3*i + 2];

        for (int j = i + 1 + t; j < N; j += 256) {
            float dx = P[3*j + 0] - xi;
            float dy = P[3*j + 1] - yi;
            float dz = P[3*j + 2] - zi;
            float d2;
            if (diag) {
                dx -= Lx * rintf(dx * iLx);
                dy -= Ly * rintf(dy * iLy);
                dz -= Lz * rintf(dz * iLz);
                d2 = dx*dx + dy*dy + dz*dz;
            } else {
                float fx = dx*s_ci[0] + dy*s_ci[3] + dz*s_ci[6];
                float fy = dx*s_ci[1] + dy*s_ci[4] + dz*s_ci[7];
                float fz = dx*s_ci[2] + dy*s_ci[5] + dz*s_ci[8];
                fx -= rintf(fx); fy -= rintf(fy); fz -= rintf(fz);
                float mx = fx*s_c[0] + fy*s_c[3] + fz*s_c[6];
                float my = fx*s_c[1] + fy*s_c[4] + fz*s_c[7];
                float mz = fx*s_c[2] + fy*s_c[5] + fz*s_c[8];
                d2 = mx*mx + my*my + mz*mz;
            }
            // exact window mask (monotone-equivalent of reference in_win)
            if (d2 <= minb2 || d2 >= maxb2) continue;
            float d = sqrtf(d2 + 1e-10f);

            // cloud-in-cell deposit between fine-bin centers c_m=(m+0.5)h
            float u  = d * INV_HF - 0.5f;
            float mf = floorf(u);
            float f  = u - mf;
            int m    = (int)mf;
            int m0   = m < 0 ? 0 : (m > M - 1 ? M - 1 : m);
            int m1   = m + 1 < 0 ? 0 : (m + 1 > M - 1 ? M - 1 : m + 1);
            atomicAdd(&g_fine[m0], 1.0f - f);
            atomicAdd(&g_fine[m1], f);
        }
    }
}

// ---------------------------------------------------------------------------
// Kernel 2: gather convolution  g_hist[k] = GNORM * sum_m fine[m] *
//           exp(-0.5*((r_k - c_m)/w)^2)   over |r_k - c_m| <= CUT
// One block per r bin, 128 threads, warp-shuffle reduction.
// ---------------------------------------------------------------------------
__global__ void __launch_bounds__(128)
conv_kernel(const float* __restrict__ rb, int nb) {
    __shared__ float s_red[4];
    int k = blockIdx.x;
    int t = threadIdx.x;
    float r = rb[k];
    float maxb = rb[nb - 1] + 3.0f * WKER;
    int M = (int)ceilf(maxb * INV_HF) + 1;
    if (M > MFINE_MAX) M = MFINE_MAX;

    int mlo = (int)ceilf ((r - CUT) * INV_HF - 0.5f);
    int mhi = (int)floorf((r + CUT) * INV_HF - 0.5f);
    mlo = mlo < 0 ? 0 : mlo;
    mhi = mhi > M - 1 ? M - 1 : mhi;

    float acc = 0.0f;
    for (int m = mlo + t; m <= mhi; m += 128) {
        float c = ((float)m + 0.5f) * HF;
        float u = (r - c) * INV_WKER;
        acc += g_fine[m] * __expf(-0.5f * u * u);
    }
    #pragma unroll
    for (int o = 16; o > 0; o >>= 1)
        acc += __shfl_xor_sync(0xffffffff, acc, o);
    if ((t & 31) == 0) s_red[t >> 5] = acc;
    __syncthreads();
    if (t == 0)
        g_hist[k] = GNORM * (s_red[0] + s_red[1] + s_red[2] + s_red[3]);
}

// ---------------------------------------------------------------------------
// Kernel 3 (fused G + S + F):
//   A_k = 4*pi*rho * w_k * r_k * G_k  (trapezoid weights w_k) in shared,
//   S(Q) = 1 + (1/(Q+1e-10)) * sum_k A_k sin(Q r_k);  F(Q) = Q (S-1).
// ---------------------------------------------------------------------------
__global__ void __launch_bounds__(128)
sf_kernel(const float* __restrict__ cell, const float* __restrict__ rb,
          const float* __restrict__ qb, float* __restrict__ out,
          int nb, int N, float n_pairs) {
    __shared__ float sA[NB_MAX];
    __shared__ float sR[NB_MAX];
    __shared__ float s_red[4];
    int q = blockIdx.x;
    int t = threadIdx.x;

    float m0 = cell[0], m1 = cell[1], m2 = cell[2];
    float m3 = cell[3], m4 = cell[4], m5 = cell[5];
    float m6 = cell[6], m7 = cell[7], m8 = cell[8];
    float det = m0*(m4*m8 - m5*m7) - m1*(m3*m8 - m5*m6) + m2*(m3*m7 - m4*m6);
    float vol = fabsf(det);

    float pref  = vol / n_pairs / (4.0f * PI_F);
    float coeff = 5.803f * 5.803f * 0.01f;
    float rho4p = 4.0f * PI_F * ((float)N / vol);

    for (int k = t; k < nb; k += 128) {
        float r  = rb[k];
        float gp = pref * g_hist[k] / (r * r);
        float G  = coeff * (gp - 1.0f);
        if (q == 0) out[k] = G;
        float xm = (k > 0)      ? rb[k - 1] : r;
        float xp = (k < nb - 1) ? rb[k + 1] : r;
        sA[k] = rho4p * 0.5f * (xp - xm) * r * G;
        sR[k] = r;
    }
    __syncthreads();

    float Q    = qb[q];
    float invq = 1.0f / (Q + 1e-10f);
    float acc  = 0.0f;
    for (int k = t; k < nb; k += 128)
        acc += sA[k] * sinf(Q * sR[k]);

    #pragma unroll
    for (int o = 16; o > 0; o >>= 1)
        acc += __shfl_xor_sync(0xffffffff, acc, o);
    if ((t & 31) == 0) s_red[t >> 5] = acc;
    __syncthreads();
    if (t == 0) {
        float s = s_red[0] + s_red[1] + s_red[2] + s_red[3];
        float S = 1.0f + invq * s;
        out[nb + q]     = S;
        out[2 * nb + q] = Q * (S - 1.0f);
    }
}

// ---------------------------------------------------------------------------
extern "C" void kernel_launch(void* const* d_in, const int* in_sizes, int n_in,
                              void* d_out, int out_size) {
    const float* pos  = (const float*)d_in[0];
    const float* cell = (const float*)d_in[1];
    const float* rb   = (const float*)d_in[2];
    const float* qb   = (const float*)d_in[3];
    float* out = (float*)d_out;

    int N  = in_sizes[0] / 3;
    int nb = in_sizes[2];
    float n_pairs = 0.5f * (float)N * (float)(N - 1);

    void* fineptr = 0;
    cudaGetSymbolAddress(&fineptr, g_fine);
    cudaMemsetAsync(fineptr, 0, MFINE_MAX * sizeof(float));

    hist_kernel<<<(N + 1) / 2, 256>>>(pos, cell, rb, N, nb);
    conv_kernel<<<nb, 128>>>(rb, nb);
    sf_kernel<<<nb, 128>>>(cell, rb, qb, out, nb, N, n_pairs);
}

// round 8
// speedup vs baseline: 1.0022x; 1.0022x over previous
#include <cuda_runtime.h>
#include <math.h>

#define NB_MAX 400
#define NMAX   1024
#define WKER   0.05f
#define INV_WKER 20.0f
#define CUT    0.225f          // 4.5 sigma truncation
#define GNORM  7.9788456080f   // 1/(0.05*sqrt(2*pi))
#define PI_F   3.14159265358979f
#define HF     0.0025f         // fine-bin width = sigma/20
#define INV_HF 400.0f
#define MFINE_MAX 4608
#define HBLK   128             // hist grid size
#define ROWPAIRS_PER_BLK 4

__device__ float g_fine[MFINE_MAX];   // CIC pair cloud (zero at load; sf re-zeroes)
__device__ float g_hist[NB_MAX];      // KDE result (fully written by conv)

// ---------------------------------------------------------------------------
// Kernel 1: MIC pair distances + CIC deposit into fine histogram.
// Block b owns row-pairs (i, N-1-i) for i = 4b..4b+3  -> 4(N-1) pairs/block,
// 16 pairs/thread. 2 fire-and-forget global atomics per in-window pair.
// ---------------------------------------------------------------------------
__global__ void __launch_bounds__(256)
hist_kernel(const float* __restrict__ pos, const float* __restrict__ cell,
            const float* __restrict__ rb, int N, int nb) {
    __shared__ float s_pos[NMAX * 3];
    __shared__ float s_ci[9];
    __shared__ float s_c[9];
    __shared__ int   s_diag;
    int t = threadIdx.x;

    bool fits = (N <= NMAX);
    if (fits)
        for (int k = t; k < 3 * N; k += 256) s_pos[k] = pos[k];
    if (t == 0) {
        float m[9];
        #pragma unroll
        for (int i = 0; i < 9; i++) { m[i] = cell[i]; s_c[i] = m[i]; }
        float c00 =  (m[4]*m[8] - m[5]*m[7]);
        float c01 = -(m[3]*m[8] - m[5]*m[6]);
        float c02 =  (m[3]*m[7] - m[4]*m[6]);
        float det = m[0]*c00 + m[1]*c01 + m[2]*c02;
        float id  = 1.0f / det;
        s_ci[0] =  c00 * id;
        s_ci[1] = -(m[1]*m[8] - m[2]*m[7]) * id;
        s_ci[2] =  (m[1]*m[5] - m[2]*m[4]) * id;
        s_ci[3] =  c01 * id;
        s_ci[4] =  (m[0]*m[8] - m[2]*m[6]) * id;
        s_ci[5] = -(m[0]*m[5] - m[2]*m[3]) * id;
        s_ci[6] =  c02 * id;
        s_ci[7] = -(m[0]*m[7] - m[1]*m[6]) * id;
        s_ci[8] =  (m[0]*m[4] - m[1]*m[3]) * id;
        s_diag = (m[1]==0.f && m[2]==0.f && m[3]==0.f &&
                  m[5]==0.f && m[6]==0.f && m[7]==0.f) ? 1 : 0;
    }
    __syncthreads();

    const float* __restrict__ P = fits ? s_pos : pos;

    const float minb  = rb[0]      - 3.0f * WKER;
    const float maxb  = rb[nb - 1] + 3.0f * WKER;
    const float minb2 = (minb > 0.0f) ? minb * minb : -1.0f;
    const float maxb2 = maxb * maxb;
    int  M = (int)ceilf(maxb * INV_HF) + 1;
    if (M > MFINE_MAX) M = MFINE_MAX;
    const bool diag = (s_diag != 0);
    const float Lx = s_c[0], Ly = s_c[4], Lz = s_c[8];
    const float iLx = 1.0f / Lx, iLy = 1.0f / Ly, iLz = 1.0f / Lz;

    #pragma unroll
    for (int h = 0; h < 2 * ROWPAIRS_PER_BLK; h++) {
        int r = (int)blockIdx.x * ROWPAIRS_PER_BLK + (h >> 1);
        int i = (h & 1) ? (N - 1 - r) : r;
        if ((h & 1) && i <= r) continue;       // avoid double-count if N odd edge
        if (i < 0 || i >= N - 1) continue;
        float xi = P[3*i + 0], yi = P[3*i + 1], zi = P[3*i + 2];

        for (int j = i + 1 + t; j < N; j += 256) {
            float dx = P[3*j + 0] - xi;
            float dy = P[3*j + 1] - yi;
            float dz = P[3*j + 2] - zi;
            float d2;
            if (diag) {
                dx -= Lx * rintf(dx * iLx);
                dy -= Ly * rintf(dy * iLy);
                dz -= Lz * rintf(dz * iLz);
                d2 = dx*dx + dy*dy + dz*dz;
            } else {
                float fx = dx*s_ci[0] + dy*s_ci[3] + dz*s_ci[6];
                float fy = dx*s_ci[1] + dy*s_ci[4] + dz*s_ci[7];
                float fz = dx*s_ci[2] + dy*s_ci[5] + dz*s_ci[8];
                fx -= rintf(fx); fy -= rintf(fy); fz -= rintf(fz);
                float mx = fx*s_c[0] + fy*s_c[3] + fz*s_c[6];
                float my = fx*s_c[1] + fy*s_c[4] + fz*s_c[7];
                float mz = fx*s_c[2] + fy*s_c[5] + fz*s_c[8];
                d2 = mx*mx + my*my + mz*mz;
            }
            // exact window mask (monotone-equivalent of reference in_win)
            if (d2 <= minb2 || d2 >= maxb2) continue;
            float d = sqrtf(d2 + 1e-10f);

            // cloud-in-cell deposit between fine-bin centers c_m=(m+0.5)h
            float u  = d * INV_HF - 0.5f;
            float mf = floorf(u);
            float f  = u - mf;
            int m    = (int)mf;
            int m0   = m < 0 ? 0 : (m > M - 1 ? M - 1 : m);
            int m1   = m + 1 < 0 ? 0 : (m + 1 > M - 1 ? M - 1 : m + 1);
            atomicAdd(&g_fine[m0], 1.0f - f);
            atomicAdd(&g_fine[m1], f);
        }
    }
}

// ---------------------------------------------------------------------------
// Kernel 2: gather convolution  g_hist[k] = GNORM * sum_m fine[m] *
//           exp(-0.5*((r_k - c_m)/w)^2)   over |r_k - c_m| <= CUT
// ---------------------------------------------------------------------------
__global__ void __launch_bounds__(128)
conv_kernel(const float* __restrict__ rb, int nb) {
    __shared__ float s_red[4];
    int k = blockIdx.x;
    int t = threadIdx.x;
    float r = rb[k];
    float maxb = rb[nb - 1] + 3.0f * WKER;
    int M = (int)ceilf(maxb * INV_HF) + 1;
    if (M > MFINE_MAX) M = MFINE_MAX;

    int mlo = (int)ceilf ((r - CUT) * INV_HF - 0.5f);
    int mhi = (int)floorf((r + CUT) * INV_HF - 0.5f);
    mlo = mlo < 0 ? 0 : mlo;
    mhi = mhi > M - 1 ? M - 1 : mhi;

    float acc = 0.0f;
    for (int m = mlo + t; m <= mhi; m += 128) {
        float c = ((float)m + 0.5f) * HF;
        float u = (r - c) * INV_WKER;
        acc += g_fine[m] * __expf(-0.5f * u * u);
    }
    #pragma unroll
    for (int o = 16; o > 0; o >>= 1)
        acc += __shfl_xor_sync(0xffffffff, acc, o);
    if ((t & 31) == 0) s_red[t >> 5] = acc;
    __syncthreads();
    if (t == 0)
        g_hist[k] = GNORM * (s_red[0] + s_red[1] + s_red[2] + s_red[3]);
}

// ---------------------------------------------------------------------------
// Kernel 3 (fused G + S + F), also re-zeroes g_fine for the next replay
// (conv has already consumed it; __device__ globals start zeroed at load).
// ---------------------------------------------------------------------------
__global__ void __launch_bounds__(128)
sf_kernel(const float* __restrict__ cell, const float* __restrict__ rb,
          const float* __restrict__ qb, float* __restrict__ out,
          int nb, int N, float n_pairs) {
    __shared__ float sA[NB_MAX];
    __shared__ float sR[NB_MAX];
    __shared__ float s_red[4];
    int q = blockIdx.x;
    int t = threadIdx.x;

    // reset the fine histogram (blocks 0..35 cover 4608 entries)
    {
        int idx = q * 128 + t;
        if (idx < MFINE_MAX) g_fine[idx] = 0.0f;
    }

    float m0 = cell[0], m1 = cell[1], m2 = cell[2];
    float m3 = cell[3], m4 = cell[4], m5 = cell[5];
    float m6 = cell[6], m7 = cell[7], m8 = cell[8];
    float det = m0*(m4*m8 - m5*m7) - m1*(m3*m8 - m5*m6) + m2*(m3*m7 - m4*m6);
    float vol = fabsf(det);

    float pref  = vol / n_pairs / (4.0f * PI_F);
    float coeff = 5.803f * 5.803f * 0.01f;
    float rho4p = 4.0f * PI_F * ((float)N / vol);

    for (int k = t; k < nb; k += 128) {
        float r  = rb[k];
        float gp = pref * g_hist[k] / (r * r);
        float G  = coeff * (gp - 1.0f);
        if (q == 0) out[k] = G;
        float xm = (k > 0)      ? rb[k - 1] : r;
        float xp = (k < nb - 1) ? rb[k + 1] : r;
        sA[k] = rho4p * 0.5f * (xp - xm) * r * G;
        sR[k] = r;
    }
    __syncthreads();

    float Q    = qb[q];
    float invq = 1.0f / (Q + 1e-10f);
    float acc  = 0.0f;
    for (int k = t; k < nb; k += 128)
        acc += sA[k] * sinf(Q * sR[k]);

    #pragma unroll
    for (int o = 16; o > 0; o >>= 1)
        acc += __shfl_xor_sync(0xffffffff, acc, o);
    if ((t & 31) == 0) s_red[t >> 5] = acc;
    __syncthreads();
    if (t == 0) {
        float s = s_red[0] + s_red[1] + s_red[2] + s_red[3];
        float S = 1.0f + invq * s;
        out[nb + q]     = S;
        out[2 * nb + q] = Q * (S - 1.0f);
    }
}

// ---------------------------------------------------------------------------
extern "C" void kernel_launch(void* const* d_in, const int* in_sizes, int n_in,
                              void* d_out, int out_size) {
    const float* pos  = (const float*)d_in[0];
    const float* cell = (const float*)d_in[1];
    const float* rb   = (const float*)d_in[2];
    const float* qb   = (const float*)d_in[3];
    float* out = (float*)d_out;

    int N  = in_sizes[0] / 3;
    int nb = in_sizes[2];
    float n_pairs = 0.5f * (float)N * (float)(N - 1);

    int nblk = (N + 2 * ROWPAIRS_PER_BLK - 1) / (2 * ROWPAIRS_PER_BLK);
    hist_kernel<<<nblk, 256>>>(pos, cell, rb, N, nb);
    conv_kernel<<<nb, 128>>>(rb, nb);
    sf_kernel<<<nb, 128>>>(cell, rb, qb, out, nb, N, n_pairs);
}

// round 9
// speedup vs baseline: 1.4295x; 1.4263x over previous
#include <cuda_runtime.h>
#include <math.h>

#define NB_MAX 400
#define NMAX   1024
#define WKER   0.05f
#define INV_WKER 20.0f
#define CUT    0.225f          // 4.5 sigma truncation
#define GNORM  7.9788456080f   // 1/(0.05*sqrt(2*pi))
#define PI_F   3.14159265358979f
#define HF     0.005f          // fine-bin width = sigma/10
#define INV_HF 200.0f
#define MFINE_MAX 2304
#define ROWPAIRS_PER_BLK 4

__device__ float g_fine[MFINE_MAX];   // CIC pair cloud (zero at load; sf re-zeroes)
__device__ float g_hist[NB_MAX];      // KDE result (fully written by conv)

// ---------------------------------------------------------------------------
// Kernel 1: MIC pair distances + CIC deposit into a PER-BLOCK shared fine
// histogram (smem atomics, spread-addr floor), then one coalesced
// distinct-address global merge. No contended L2 atomics.
// Block b owns row-pairs (i, N-1-i) for i = 4b..4b+3 -> 4(N-1) pairs/block.
// ---------------------------------------------------------------------------
__global__ void __launch_bounds__(256)
hist_kernel(const float* __restrict__ pos, const float* __restrict__ cell,
            const float* __restrict__ rb, int N, int nb) {
    __shared__ float s_pos[NMAX * 3];
    __shared__ float s_fine[MFINE_MAX];
    __shared__ float s_ci[9];
    __shared__ float s_c[9];
    __shared__ int   s_diag;
    int t = threadIdx.x;

    bool fits = (N <= NMAX);
    if (fits)
        for (int k = t; k < 3 * N; k += 256) s_pos[k] = pos[k];
    for (int k = t; k < MFINE_MAX; k += 256) s_fine[k] = 0.0f;
    if (t == 0) {
        float m[9];
        #pragma unroll
        for (int i = 0; i < 9; i++) { m[i] = cell[i]; s_c[i] = m[i]; }
        float c00 =  (m[4]*m[8] - m[5]*m[7]);
        float c01 = -(m[3]*m[8] - m[5]*m[6]);
        float c02 =  (m[3]*m[7] - m[4]*m[6]);
        float det = m[0]*c00 + m[1]*c01 + m[2]*c02;
        float id  = 1.0f / det;
        s_ci[0] =  c00 * id;
        s_ci[1] = -(m[1]*m[8] - m[2]*m[7]) * id;
        s_ci[2] =  (m[1]*m[5] - m[2]*m[4]) * id;
        s_ci[3] =  c01 * id;
        s_ci[4] =  (m[0]*m[8] - m[2]*m[6]) * id;
        s_ci[5] = -(m[0]*m[5] - m[2]*m[3]) * id;
        s_ci[6] =  c02 * id;
        s_ci[7] = -(m[0]*m[7] - m[1]*m[6]) * id;
        s_ci[8] =  (m[0]*m[4] - m[1]*m[3]) * id;
        s_diag = (m[1]==0.f && m[2]==0.f && m[3]==0.f &&
                  m[5]==0.f && m[6]==0.f && m[7]==0.f) ? 1 : 0;
    }
    __syncthreads();

    const float* __restrict__ P = fits ? s_pos : pos;

    const float minb  = rb[0]      - 3.0f * WKER;
    const float maxb  = rb[nb - 1] + 3.0f * WKER;
    const float minb2 = (minb > 0.0f) ? minb * minb : -1.0f;
    const float maxb2 = maxb * maxb;
    int  M = (int)ceilf(maxb * INV_HF) + 1;
    if (M > MFINE_MAX) M = MFINE_MAX;
    const bool diag = (s_diag != 0);
    const float Lx = s_c[0], Ly = s_c[4], Lz = s_c[8];
    const float iLx = 1.0f / Lx, iLy = 1.0f / Ly, iLz = 1.0f / Lz;

    #pragma unroll
    for (int h = 0; h < 2 * ROWPAIRS_PER_BLK; h++) {
        int r = (int)blockIdx.x * ROWPAIRS_PER_BLK + (h >> 1);
        int i = (h & 1) ? (N - 1 - r) : r;
        if ((h & 1) && i <= r) continue;       // no double-count on middle row
        if (i < 0 || i >= N - 1) continue;
        float xi = P[3*i + 0], yi = P[3*i + 1], zi = P[3*i + 2];

        for (int j = i + 1 + t; j < N; j += 256) {
            float dx = P[3*j + 0] - xi;
            float dy = P[3*j + 1] - yi;
            float dz = P[3*j + 2] - zi;
            float d2;
            if (diag) {
                dx -= Lx * rintf(dx * iLx);
                dy -= Ly * rintf(dy * iLy);
                dz -= Lz * rintf(dz * iLz);
                d2 = dx*dx + dy*dy + dz*dz;
            } else {
                float fx = dx*s_ci[0] + dy*s_ci[3] + dz*s_ci[6];
                float fy = dx*s_ci[1] + dy*s_ci[4] + dz*s_ci[7];
                float fz = dx*s_ci[2] + dy*s_ci[5] + dz*s_ci[8];
                fx -= rintf(fx); fy -= rintf(fy); fz -= rintf(fz);
                float mx = fx*s_c[0] + fy*s_c[3] + fz*s_c[6];
                float my = fx*s_c[1] + fy*s_c[4] + fz*s_c[7];
                float mz = fx*s_c[2] + fy*s_c[5] + fz*s_c[8];
                d2 = mx*mx + my*my + mz*mz;
            }
            // exact window mask (monotone-equivalent of reference in_win)
            if (d2 <= minb2 || d2 >= maxb2) continue;
            float d = sqrtf(d2 + 1e-10f);

            // cloud-in-cell deposit between fine-bin centers c_m=(m+0.5)h
            float u  = d * INV_HF - 0.5f;
            float mf = floorf(u);
            float f  = u - mf;
            int m    = (int)mf;
            int m0   = m < 0 ? 0 : (m > M - 1 ? M - 1 : m);
            int m1   = m + 1 < 0 ? 0 : (m + 1 > M - 1 ? M - 1 : m + 1);
            atomicAdd(&s_fine[m0], 1.0f - f);
            atomicAdd(&s_fine[m1], f);
        }
    }
    __syncthreads();

    // coalesced, distinct-address merge into global
    for (int k = t; k < M; k += 256) {
        float v = s_fine[k];
        if (v != 0.0f) atomicAdd(&g_fine[k], v);
    }
}

// ---------------------------------------------------------------------------
// Kernel 2: gather convolution  g_hist[k] = GNORM * sum_m fine[m] *
//           exp(-0.5*((r_k - c_m)/w)^2)   over |r_k - c_m| <= CUT
// ---------------------------------------------------------------------------
__global__ void __launch_bounds__(128)
conv_kernel(const float* __restrict__ rb, int nb) {
    __shared__ float s_red[4];
    int k = blockIdx.x;
    int t = threadIdx.x;
    float r = rb[k];
    float maxb = rb[nb - 1] + 3.0f * WKER;
    int M = (int)ceilf(maxb * INV_HF) + 1;
    if (M > MFINE_MAX) M = MFINE_MAX;

    int mlo = (int)ceilf ((r - CUT) * INV_HF - 0.5f);
    int mhi = (int)floorf((r + CUT) * INV_HF - 0.5f);
    mlo = mlo < 0 ? 0 : mlo;
    mhi = mhi > M - 1 ? M - 1 : mhi;

    float acc = 0.0f;
    for (int m = mlo + t; m <= mhi; m += 128) {
        float c = ((float)m + 0.5f) * HF;
        float u = (r - c) * INV_WKER;
        acc += g_fine[m] * __expf(-0.5f * u * u);
    }
    #pragma unroll
    for (int o = 16; o > 0; o >>= 1)
        acc += __shfl_xor_sync(0xffffffff, acc, o);
    if ((t & 31) == 0) s_red[t >> 5] = acc;
    __syncthreads();
    if (t == 0)
        g_hist[k] = GNORM * (s_red[0] + s_red[1] + s_red[2] + s_red[3]);
}

// ---------------------------------------------------------------------------
// Kernel 3 (fused G + S + F), also re-zeroes g_fine for the next replay
// (conv has already consumed it; __device__ globals start zeroed at load).
// ---------------------------------------------------------------------------
__global__ void __launch_bounds__(128)
sf_kernel(const float* __restrict__ cell, const float* __restrict__ rb,
          const float* __restrict__ qb, float* __restrict__ out,
          int nb, int N, float n_pairs) {
    __shared__ float sA[NB_MAX];
    __shared__ float sR[NB_MAX];
    __shared__ float s_red[4];
    int q = blockIdx.x;
    int t = threadIdx.x;

    // reset the fine histogram (first 18 blocks cover 2304 entries)
    {
        int idx = q * 128 + t;
        if (idx < MFINE_MAX) g_fine[idx] = 0.0f;
    }

    float m0 = cell[0], m1 = cell[1], m2 = cell[2];
    float m3 = cell[3], m4 = cell[4], m5 = cell[5];
    float m6 = cell[6], m7 = cell[7], m8 = cell[8];
    float det = m0*(m4*m8 - m5*m7) - m1*(m3*m8 - m5*m6) + m2*(m3*m7 - m4*m6);
    float vol = fabsf(det);

    float pref  = vol / n_pairs / (4.0f * PI_F);
    float coeff = 5.803f * 5.803f * 0.01f;
    float rho4p = 4.0f * PI_F * ((float)N / vol);

    for (int k = t; k < nb; k += 128) {
        float r  = rb[k];
        float gp = pref * g_hist[k] / (r * r);
        float G  = coeff * (gp - 1.0f);
        if (q == 0) out[k] = G;
        float xm = (k > 0)      ? rb[k - 1] : r;
        float xp = (k < nb - 1) ? rb[k + 1] : r;
        sA[k] = rho4p * 0.5f * (xp - xm) * r * G;
        sR[k] = r;
    }
    __syncthreads();

    float Q    = qb[q];
    float invq = 1.0f / (Q + 1e-10f);
    float acc  = 0.0f;
    for (int k = t; k < nb; k += 128)
        acc += sA[k] * sinf(Q * sR[k]);

    #pragma unroll
    for (int o = 16; o > 0; o >>= 1)
        acc += __shfl_xor_sync(0xffffffff, acc, o);
    if ((t & 31) == 0) s_red[t >> 5] = acc;
    __syncthreads();
    if (t == 0) {
        float s = s_red[0] + s_red[1] + s_red[2] + s_red[3];
        float S = 1.0f + invq * s;
        out[nb + q]     = S;
        out[2 * nb + q] = Q * (S - 1.0f);
    }
}

// ---------------------------------------------------------------------------
extern "C" void kernel_launch(void* const* d_in, const int* in_sizes, int n_in,
                              void* d_out, int out_size) {
    const float* pos  = (const float*)d_in[0];
    const float* cell = (const float*)d_in[1];
    const float* rb   = (const float*)d_in[2];
    const float* qb   = (const float*)d_in[3];
    float* out = (float*)d_out;

    int N  = in_sizes[0] / 3;
    int nb = in_sizes[2];
    float n_pairs = 0.5f * (float)N * (float)(N - 1);

    int nblk = (N + 2 * ROWPAIRS_PER_BLK - 1) / (2 * ROWPAIRS_PER_BLK);
    hist_kernel<<<nblk, 256>>>(pos, cell, rb, N, nb);
    conv_kernel<<<nb, 128>>>(rb, nb);
    sf_kernel<<<nb, 128>>>(cell, rb, qb, out, nb, N, n_pairs);
}

// round 10
// speedup vs baseline: 1.5050x; 1.0528x over previous
#include <cuda_runtime.h>
#include <math.h>

#define NB_MAX 400
#define NMAX   1024
#define WKER   0.05f
#define INV_WKER 20.0f
#define CUT    0.225f          // 4.5 sigma truncation
#define GNORM  7.9788456080f   // 1/(0.05*sqrt(2*pi))
#define PI_F   3.14159265358979f
#define HF     0.005f          // fine-bin width = sigma/10
#define INV_HF 200.0f
#define MFINE_MAX 2304
#define ROWPAIRS_PER_BLK 2

__device__ float g_fine[MFINE_MAX];   // CIC pair cloud (zero at load; sf re-zeroes)
__device__ float g_hist[NB_MAX];      // KDE result (fully written by conv)

// ---------------------------------------------------------------------------
// Kernel 1: MIC pair distances + CIC deposit into a PER-BLOCK shared fine
// histogram (smem atomics, spread-addr floor), then one coalesced
// distinct-address global merge. grid=256 so ~2 blocks/SM (occupancy was
// grid-limited at 128 blocks).
// Block b owns row-pairs (i, N-1-i) for i = 2b..2b+1 -> 2(N-1) pairs/block.
// ---------------------------------------------------------------------------
__global__ void __launch_bounds__(256)
hist_kernel(const float* __restrict__ pos, const float* __restrict__ cell,
            const float* __restrict__ rb, int N, int nb) {
    __shared__ float s_pos[NMAX * 3];
    __shared__ float s_fine[MFINE_MAX];
    __shared__ float s_ci[9];
    __shared__ float s_c[9];
    __shared__ int   s_diag;
    int t = threadIdx.x;

    bool fits = (N <= NMAX);
    if (fits)
        for (int k = t; k < 3 * N; k += 256) s_pos[k] = pos[k];
    for (int k = t; k < MFINE_MAX; k += 256) s_fine[k] = 0.0f;
    if (t == 0) {
        float m[9];
        #pragma unroll
        for (int i = 0; i < 9; i++) { m[i] = cell[i]; s_c[i] = m[i]; }
        float c00 =  (m[4]*m[8] - m[5]*m[7]);
        float c01 = -(m[3]*m[8] - m[5]*m[6]);
        float c02 =  (m[3]*m[7] - m[4]*m[6]);
        float det = m[0]*c00 + m[1]*c01 + m[2]*c02;
        float id  = 1.0f / det;
        s_ci[0] =  c00 * id;
        s_ci[1] = -(m[1]*m[8] - m[2]*m[7]) * id;
        s_ci[2] =  (m[1]*m[5] - m[2]*m[4]) * id;
        s_ci[3] =  c01 * id;
        s_ci[4] =  (m[0]*m[8] - m[2]*m[6]) * id;
        s_ci[5] = -(m[0]*m[5] - m[2]*m[3]) * id;
        s_ci[6] =  c02 * id;
        s_ci[7] = -(m[0]*m[7] - m[1]*m[6]) * id;
        s_ci[8] =  (m[0]*m[4] - m[1]*m[3]) * id;
        s_diag = (m[1]==0.f && m[2]==0.f && m[3]==0.f &&
                  m[5]==0.f && m[6]==0.f && m[7]==0.f) ? 1 : 0;
    }
    __syncthreads();

    const float* __restrict__ P = fits ? s_pos : pos;

    const float minb  = rb[0]      - 3.0f * WKER;
    const float maxb  = rb[nb - 1] + 3.0f * WKER;
    const float minb2 = (minb > 0.0f) ? minb * minb : -1.0f;
    const float maxb2 = maxb * maxb;
    int  M = (int)ceilf(maxb * INV_HF) + 1;
    if (M > MFINE_MAX) M = MFINE_MAX;
    const bool diag = (s_diag != 0);
    const float Lx = s_c[0], Ly = s_c[4], Lz = s_c[8];
    const float iLx = 1.0f / Lx, iLy = 1.0f / Ly, iLz = 1.0f / Lz;

    #pragma unroll
    for (int h = 0; h < 2 * ROWPAIRS_PER_BLK; h++) {
        int r = (int)blockIdx.x * ROWPAIRS_PER_BLK + (h >> 1);
        int i = (h & 1) ? (N - 1 - r) : r;
        if ((h & 1) && i <= r) continue;       // no double-count on middle row
        if (i < 0 || i >= N - 1) continue;
        float xi = P[3*i + 0], yi = P[3*i + 1], zi = P[3*i + 2];

        #pragma unroll 2
        for (int j = i + 1 + t; j < N; j += 256) {
            float dx = P[3*j + 0] - xi;
            float dy = P[3*j + 1] - yi;
            float dz = P[3*j + 2] - zi;
            float d2;
            if (diag) {
                dx -= Lx * rintf(dx * iLx);
                dy -= Ly * rintf(dy * iLy);
                dz -= Lz * rintf(dz * iLz);
                d2 = dx*dx + dy*dy + dz*dz;
            } else {
                float fx = dx*s_ci[0] + dy*s_ci[3] + dz*s_ci[6];
                float fy = dx*s_ci[1] + dy*s_ci[4] + dz*s_ci[7];
                float fz = dx*s_ci[2] + dy*s_ci[5] + dz*s_ci[8];
                fx -= rintf(fx); fy -= rintf(fy); fz -= rintf(fz);
                float mx = fx*s_c[0] + fy*s_c[3] + fz*s_c[6];
                float my = fx*s_c[1] + fy*s_c[4] + fz*s_c[7];
                float mz = fx*s_c[2] + fy*s_c[5] + fz*s_c[8];
                d2 = mx*mx + my*my + mz*mz;
            }
            // exact window mask (monotone-equivalent of reference in_win)
            if (d2 <= minb2 || d2 >= maxb2) continue;
            float d = sqrtf(d2 + 1e-10f);

            // cloud-in-cell deposit between fine-bin centers c_m=(m+0.5)h
            float u  = d * INV_HF - 0.5f;
            float mf = floorf(u);
            float f  = u - mf;
            int m    = (int)mf;
            int m0   = m < 0 ? 0 : (m > M - 1 ? M - 1 : m);
            int m1   = m + 1 < 0 ? 0 : (m + 1 > M - 1 ? M - 1 : m + 1);
            atomicAdd(&s_fine[m0], 1.0f - f);
            atomicAdd(&s_fine[m1], f);
        }
    }
    __syncthreads();

    // coalesced, distinct-address merge into global
    for (int k = t; k < M; k += 256) {
        float v = s_fine[k];
        if (v != 0.0f) atomicAdd(&g_fine[k], v);
    }
}

// ---------------------------------------------------------------------------
// Kernel 2: gather convolution  g_hist[k] = GNORM * sum_m fine[m] *
//           exp(-0.5*((r_k - c_m)/w)^2)   over |r_k - c_m| <= CUT
// ---------------------------------------------------------------------------
__global__ void __launch_bounds__(128)
conv_kernel(const float* __restrict__ rb, int nb) {
    __shared__ float s_red[4];
    int k = blockIdx.x;
    int t = threadIdx.x;
    float r = rb[k];
    float maxb = rb[nb - 1] + 3.0f * WKER;
    int M = (int)ceilf(maxb * INV_HF) + 1;
    if (M > MFINE_MAX) M = MFINE_MAX;

    int mlo = (int)ceilf ((r - CUT) * INV_HF - 0.5f);
    int mhi = (int)floorf((r + CUT) * INV_HF - 0.5f);
    mlo = mlo < 0 ? 0 : mlo;
    mhi = mhi > M - 1 ? M - 1 : mhi;

    float acc = 0.0f;
    for (int m = mlo + t; m <= mhi; m += 128) {
        float c = ((float)m + 0.5f) * HF;
        float u = (r - c) * INV_WKER;
        acc += g_fine[m] * __expf(-0.5f * u * u);
    }
    #pragma unroll
    for (int o = 16; o > 0; o >>= 1)
        acc += __shfl_xor_sync(0xffffffff, acc, o);
    if ((t & 31) == 0) s_red[t >> 5] = acc;
    __syncthreads();
    if (t == 0)
        g_hist[k] = GNORM * (s_red[0] + s_red[1] + s_red[2] + s_red[3]);
}

// ---------------------------------------------------------------------------
// Kernel 3 (fused G + S + F), also re-zeroes g_fine for the next replay
// (conv has already consumed it; __device__ globals start zeroed at load).
// ---------------------------------------------------------------------------
__global__ void __launch_bounds__(128)
sf_kernel(const float* __restrict__ cell, const float* __restrict__ rb,
          const float* __restrict__ qb, float* __restrict__ out,
          int nb, int N, float n_pairs) {
    __shared__ float sA[NB_MAX];
    __shared__ float sR[NB_MAX];
    __shared__ float s_red[4];
    int q = blockIdx.x;
    int t = threadIdx.x;

    // reset the fine histogram (first 18 blocks cover 2304 entries)
    {
        int idx = q * 128 + t;
        if (idx < MFINE_MAX) g_fine[idx] = 0.0f;
    }

    float m0 = cell[0], m1 = cell[1], m2 = cell[2];
    float m3 = cell[3], m4 = cell[4], m5 = cell[5];
    float m6 = cell[6], m7 = cell[7], m8 = cell[8];
    float det = m0*(m4*m8 - m5*m7) - m1*(m3*m8 - m5*m6) + m2*(m3*m7 - m4*m6);
    float vol = fabsf(det);

    float pref  = vol / n_pairs / (4.0f * PI_F);
    float coeff = 5.803f * 5.803f * 0.01f;
    float rho4p = 4.0f * PI_F * ((float)N / vol);

    for (int k = t; k < nb; k += 128) {
        float r  = rb[k];
        float gp = pref * g_hist[k] / (r * r);
        float G  = coeff * (gp - 1.0f);
        if (q == 0) out[k] = G;
        float xm = (k > 0)      ? rb[k - 1] : r;
        float xp = (k < nb - 1) ? rb[k + 1] : r;
        sA[k] = rho4p * 0.5f * (xp - xm) * r * G;
        sR[k] = r;
    }
    __syncthreads();

    float Q    = qb[q];
    float invq = 1.0f / (Q + 1e-10f);
    float acc  = 0.0f;
    for (int k = t; k < nb; k += 128)
        acc += sA[k] * sinf(Q * sR[k]);

    #pragma unroll
    for (int o = 16; o > 0; o >>= 1)
        acc += __shfl_xor_sync(0xffffffff, acc, o);
    if ((t & 31) == 0) s_red[t >> 5] = acc;
    __syncthreads();
    if (t == 0) {
        float s = s_red[0] + s_red[1] + s_red[2] + s_red[3];
        float S = 1.0f + invq * s;
        out[nb + q]     = S;
        out[2 * nb + q] = Q * (S - 1.0f);
    }
}

// ---------------------------------------------------------------------------
extern "C" void kernel_launch(void* const* d_in, const int* in_sizes, int n_in,
                              void* d_out, int out_size) {
    const float* pos  = (const float*)d_in[0];
    const float* cell = (const float*)d_in[1];
    const float* rb   = (const float*)d_in[2];
    const float* qb   = (const float*)d_in[3];
    float* out = (float*)d_out;

    int N  = in_sizes[0] / 3;
    int nb = in_sizes[2];
    float n_pairs = 0.5f * (float)N * (float)(N - 1);

    int nblk = (N + 2 * ROWPAIRS_PER_BLK - 1) / (2 * ROWPAIRS_PER_BLK);
    hist_kernel<<<nblk, 256>>>(pos, cell, rb, N, nb);
    conv_kernel<<<nb, 128>>>(rb, nb);
    sf_kernel<<<nb, 128>>>(cell, rb, qb, out, nb, N, n_pairs);
}

// round 12
// speedup vs baseline: 1.5779x; 1.0484x over previous
#include <cuda_runtime.h>
#include <math.h>

#define NB_MAX 400
#define WKER   0.05f
#define INV_WKER 20.0f
#define CUT    0.225f          // 4.5 sigma truncation
#define GNORM  7.9788456080f   // 1/(0.05*sqrt(2*pi))
#define PI_F   3.14159265358979f
#define HF     0.005f          // fine-bin width = sigma/10
#define INV_HF 200.0f
#define MFINE_MAX 2304

__device__ float g_fine[MFINE_MAX];   // CIC pair cloud (zero at load; sf re-zeroes)
__device__ float g_A[NB_MAX];         // integrand weights A_k (written by conv)

// ---------------------------------------------------------------------------
// Kernel 1: MIC pair distances + CIC deposit into a PER-BLOCK shared fine
// histogram (smem atomics), then coalesced distinct-address global merge.
// Positions read straight from L1/L2 (no smem staging); cell inverse computed
// redundantly per thread (uniform registers). Block b owns rows b and N-1-b
// -> N-1 pairs/block, 4 pairs/thread at N=1024, grid=N/2.
// ---------------------------------------------------------------------------
__global__ void __launch_bounds__(256)
hist_kernel(const float* __restrict__ pos, const float* __restrict__ cell,
            const float* __restrict__ rb, int N, int nb) {
    __shared__ float s_fine[MFINE_MAX];
    int t = threadIdx.x;

    for (int k = t; k < MFINE_MAX; k += 256) s_fine[k] = 0.0f;

    // per-thread (uniform) cell handling
    float m[9];
    #pragma unroll
    for (int i = 0; i < 9; i++) m[i] = __ldg(cell + i);
    bool diag = (m[1]==0.f && m[2]==0.f && m[3]==0.f &&
                 m[5]==0.f && m[6]==0.f && m[7]==0.f);
    float ci[9];
    {
        float c00 =  (m[4]*m[8] - m[5]*m[7]);
        float c01 = -(m[3]*m[8] - m[5]*m[6]);
        float c02 =  (m[3]*m[7] - m[4]*m[6]);
        float det = m[0]*c00 + m[1]*c01 + m[2]*c02;
        float id  = 1.0f / det;
        ci[0] =  c00 * id;
        ci[1] = -(m[1]*m[8] - m[2]*m[7]) * id;
        ci[2] =  (m[1]*m[5] - m[2]*m[4]) * id;
        ci[3] =  c01 * id;
        ci[4] =  (m[0]*m[8] - m[2]*m[6]) * id;
        ci[5] = -(m[0]*m[5] - m[2]*m[3]) * id;
        ci[6] =  c02 * id;
        ci[7] = -(m[0]*m[7] - m[1]*m[6]) * id;
        ci[8] =  (m[0]*m[4] - m[1]*m[3]) * id;
    }
    const float Lx = m[0], Ly = m[4], Lz = m[8];
    const float iLx = 1.0f / Lx, iLy = 1.0f / Ly, iLz = 1.0f / Lz;

    const float minb  = __ldg(rb)          - 3.0f * WKER;
    const float maxb  = __ldg(rb + nb - 1) + 3.0f * WKER;
    const float minb2 = (minb > 0.0f) ? minb * minb : -1.0f;
    const float maxb2 = maxb * maxb;
    int  M = (int)ceilf(maxb * INV_HF) + 1;
    if (M > MFINE_MAX) M = MFINE_MAX;

    __syncthreads();

    #pragma unroll
    for (int h = 0; h < 2; h++) {
        int r = (int)blockIdx.x;
        int i = h ? (N - 1 - r) : r;
        if (h && i <= r) continue;             // middle row double-count guard
        if (i < 0 || i >= N - 1) continue;
        float xi = __ldg(pos + 3*i + 0);
        float yi = __ldg(pos + 3*i + 1);
        float zi = __ldg(pos + 3*i + 2);

        #pragma unroll 4
        for (int j = i + 1 + t; j < N; j += 256) {
            float dx = __ldg(pos + 3*j + 0) - xi;
            float dy = __ldg(pos + 3*j + 1) - yi;
            float dz = __ldg(pos + 3*j + 2) - zi;
            float d2;
            if (diag) {
                dx -= Lx * rintf(dx * iLx);
                dy -= Ly * rintf(dy * iLy);
                dz -= Lz * rintf(dz * iLz);
                d2 = dx*dx + dy*dy + dz*dz;
            } else {
                float fx = dx*ci[0] + dy*ci[3] + dz*ci[6];
                float fy = dx*ci[1] + dy*ci[4] + dz*ci[7];
                float fz = dx*ci[2] + dy*ci[5] + dz*ci[8];
                fx -= rintf(fx); fy -= rintf(fy); fz -= rintf(fz);
                float mx = fx*m[0] + fy*m[3] + fz*m[6];
                float my = fx*m[1] + fy*m[4] + fz*m[7];
                float mz = fx*m[2] + fy*m[5] + fz*m[8];
                d2 = mx*mx + my*my + mz*mz;
            }
            // exact window mask (monotone-equivalent of reference in_win)
            if (d2 <= minb2 || d2 >= maxb2) continue;
            float d = sqrtf(d2 + 1e-10f);

            // cloud-in-cell deposit between fine-bin centers c_m=(m+0.5)h
            float u  = d * INV_HF - 0.5f;
            float mf = floorf(u);
            float f  = u - mf;
            int mm   = (int)mf;
            int m0   = mm < 0 ? 0 : (mm > M - 1 ? M - 1 : mm);
            int m1   = mm + 1 < 0 ? 0 : (mm + 1 > M - 1 ? M - 1 : mm + 1);
            atomicAdd(&s_fine[m0], 1.0f - f);
            atomicAdd(&s_fine[m1], f);
        }
    }
    __syncthreads();

    // coalesced, distinct-address merge into global
    for (int k = t; k < M; k += 256) {
        float v = s_fine[k];
        if (v != 0.0f) atomicAdd(&g_fine[k], v);
    }
}

// ---------------------------------------------------------------------------
// Kernel 2: gather convolution + G + integrand weights.
//   hist_k = GNORM * sum_m fine[m] * exp(-0.5*((r_k-c_m)/w)^2), |r_k-c_m|<=CUT
//   G_k    = coeff * (vol/n_pairs * hist_k / (4 pi r_k^2) - 1)   -> out[k]
//   A_k    = 4 pi rho * w_k * r_k * G_k                          -> g_A[k]
// ---------------------------------------------------------------------------
__global__ void __launch_bounds__(128)
conv_kernel(const float* __restrict__ cell, const float* __restrict__ rb,
            float* __restrict__ out, int nb, int N, float n_pairs) {
    __shared__ float s_red[4];
    int k = blockIdx.x;
    int t = threadIdx.x;
    float r = __ldg(rb + k);
    float maxb = __ldg(rb + nb - 1) + 3.0f * WKER;
    int M = (int)ceilf(maxb * INV_HF) + 1;
    if (M > MFINE_MAX) M = MFINE_MAX;

    int mlo = (int)ceilf ((r - CUT) * INV_HF - 0.5f);
    int mhi = (int)floorf((r + CUT) * INV_HF - 0.5f);
    mlo = mlo < 0 ? 0 : mlo;
    mhi = mhi > M - 1 ? M - 1 : mhi;

    float acc = 0.0f;
    for (int mm = mlo + t; mm <= mhi; mm += 128) {
        float c = ((float)mm + 0.5f) * HF;
        float u = (r - c) * INV_WKER;
        acc += g_fine[mm] * __expf(-0.5f * u * u);
    }
    #pragma unroll
    for (int o = 16; o > 0; o >>= 1)
        acc += __shfl_xor_sync(0xffffffff, acc, o);
    if ((t & 31) == 0) s_red[t >> 5] = acc;
    __syncthreads();
    if (t == 0) {
        float hist = GNORM * (s_red[0] + s_red[1] + s_red[2] + s_red[3]);
        float m0 = cell[0], m1 = cell[1], m2 = cell[2];
        float m3 = cell[3], m4 = cell[4], m5 = cell[5];
        float m6 = cell[6], m7 = cell[7], m8 = cell[8];
        float det = m0*(m4*m8 - m5*m7) - m1*(m3*m8 - m5*m6) + m2*(m3*m7 - m4*m6);
        float vol = fabsf(det);
        float pref  = vol / n_pairs / (4.0f * PI_F);
        float coeff = 5.803f * 5.803f * 0.01f;
        float rho4p = 4.0f * PI_F * ((float)N / vol);
        float G = coeff * (pref * hist / (r * r) - 1.0f);
        out[k] = G;
        float xm = (k > 0)      ? __ldg(rb + k - 1) : r;
        float xp = (k < nb - 1) ? __ldg(rb + k + 1) : r;
        g_A[k] = rho4p * 0.5f * (xp - xm) * r * G;
    }
}

// ---------------------------------------------------------------------------
// Kernel 3: S(Q) = 1 + (1/(Q+1e-10)) * sum_k A_k sin(Q r_k); F = Q (S-1).
// Also re-zeroes g_fine for the next graph replay.
// ---------------------------------------------------------------------------
__global__ void __launch_bounds__(128)
sf_kernel(const float* __restrict__ rb, const float* __restrict__ qb,
          float* __restrict__ out, int nb) {
    __shared__ float s_red[4];
    int q = blockIdx.x;
    int t = threadIdx.x;

    {   // reset fine histogram (first 18 blocks cover 2304 entries)
        int idx = q * 128 + t;
        if (idx < MFINE_MAX) g_fine[idx] = 0.0f;
    }

    float Q    = __ldg(qb + q);
    float invq = 1.0f / (Q + 1e-10f);
    float acc  = 0.0f;
    for (int k = t; k < nb; k += 128)
        acc += g_A[k] * sinf(Q * __ldg(rb + k));

    #pragma unroll
    for (int o = 16; o > 0; o >>= 1)
        acc += __shfl_xor_sync(0xffffffff, acc, o);
    if ((t & 31) == 0) s_red[t >> 5] = acc;
    __syncthreads();
    if (t == 0) {
        float S = 1.0f + invq * (s_red[0] + s_red[1] + s_red[2] + s_red[3]);
        out[nb + q]     = S;
        out[2 * nb + q] = Q * (S - 1.0f);
    }
}

// ---------------------------------------------------------------------------
extern "C" void kernel_launch(void* const* d_in, const int* in_sizes, int n_in,
                              void* d_out, int out_size) {
    const float* pos  = (const float*)d_in[0];
    const float* cell = (const float*)d_in[1];
    const float* rb   = (const float*)d_in[2];
    const float* qb   = (const float*)d_in[3];
    float* out = (float*)d_out;

    int N  = in_sizes[0] / 3;
    int nb = in_sizes[2];
    float n_pairs = 0.5f * (float)N * (float)(N - 1);

    hist_kernel<<<(N + 1) / 2, 256>>>(pos, cell, rb, N, nb);
    conv_kernel<<<nb, 128>>>(cell, rb, out, nb, N, n_pairs);
    sf_kernel<<<nb, 128>>>(rb, qb, out, nb);
}